// round 1
// baseline (speedup 1.0000x reference)
#include <cuda_runtime.h>
#include <math.h>

#define E 1024
#define H 16
#define DH 64
#define SEQ 2048
#define BATCH 2
#define MTOT (BATCH * SEQ)   // 4096

// Scratch (no cudaMalloc allowed) — 4 x 16 MB fp32 buffers.
__device__ float g_q[MTOT * E];
__device__ float g_k[MTOT * E];
__device__ float g_v[MTOT * E];
__device__ float g_att[MTOT * E];

// ---------------------------------------------------------------------------
// GEMM: C[M,N] = A[M,K] @ W[K,N] + bias[N], M=4096, N=K=1024
// 64x64 tile, BK=16, 256 threads, 4x4 per thread.
// ---------------------------------------------------------------------------
__global__ __launch_bounds__(256) void gemm_bias_kernel(
    const float* __restrict__ A, const float* __restrict__ W,
    const float* __restrict__ bias, float* __restrict__ C) {
    const int K = E, N = E;
    __shared__ float As[16][65];   // padded: transposed store conflict-free
    __shared__ float Bs[16][64];   // natural: coalesced store, float4 reads

    int tid = threadIdx.x;
    int tx = tid & 15, ty = tid >> 4;
    int m0 = blockIdx.y * 64, n0 = blockIdx.x * 64;

    float acc[4][4] = {};

    const float* Aptr = A + (size_t)m0 * K;
    const float* Wptr = W + n0;

    for (int k0 = 0; k0 < K; k0 += 16) {
#pragma unroll
        for (int i = 0; i < 4; i++) {
            int idx = i * 256 + tid;      // 0..1023
            int m = idx >> 4, kk = idx & 15;
            As[kk][m] = Aptr[(size_t)m * K + k0 + kk];
        }
#pragma unroll
        for (int i = 0; i < 4; i++) {
            int idx = i * 256 + tid;
            int kk = idx >> 6, n = idx & 63;
            Bs[kk][n] = Wptr[(size_t)(k0 + kk) * N + n];
        }
        __syncthreads();
#pragma unroll
        for (int kk = 0; kk < 16; kk++) {
            float av[4], bv[4];
#pragma unroll
            for (int i = 0; i < 4; i++) av[i] = As[kk][ty * 4 + i];
            float4 b4 = *(const float4*)&Bs[kk][tx * 4];
            bv[0] = b4.x; bv[1] = b4.y; bv[2] = b4.z; bv[3] = b4.w;
#pragma unroll
            for (int i = 0; i < 4; i++)
#pragma unroll
                for (int j = 0; j < 4; j++)
                    acc[i][j] += av[i] * bv[j];
        }
        __syncthreads();
    }

#pragma unroll
    for (int i = 0; i < 4; i++) {
        int m = m0 + ty * 4 + i;
#pragma unroll
        for (int j = 0; j < 4; j++) {
            int n = n0 + tx * 4 + j;
            C[(size_t)m * N + n] = acc[i][j] + bias[n];
        }
    }
}

// ---------------------------------------------------------------------------
// Flash attention: per block = 64-query tile of one (b, h).
// Online softmax; K smem tile reused for P tile.
// Dynamic smem: Qs[64][64] + Ks/Ps[64][65] + Vs[64][64] = 49408 bytes.
// ---------------------------------------------------------------------------
#define ATT_SMEM ((64 * 64 + 64 * 65 + 64 * 64) * 4)

__global__ __launch_bounds__(256) void attn_kernel(
    const float* __restrict__ Q, const float* __restrict__ Kg,
    const float* __restrict__ V, float* __restrict__ Og) {
    extern __shared__ float sm[];
    float* Qs = sm;                       // [64][64]
    float* Ks = sm + 64 * 64;             // [64][65]  (also P tile)
    float* Vs = sm + 64 * 64 + 64 * 65;   // [64][64]

    int tid = threadIdx.x;
    int tx = tid & 15, ty = tid >> 4;
    int qt = blockIdx.x;          // query tile 0..31
    int h = blockIdx.y;
    int b = blockIdx.z;
    int q0 = b * SEQ + qt * 64;   // first global query row
    int col0 = h * DH;            // head's column offset in [.,E]

    // Load Q tile (coalesced: consecutive tid -> consecutive d)
#pragma unroll
    for (int i = 0; i < 16; i++) {
        int idx = i * 256 + tid;          // 0..4095
        int r = idx >> 6, d = idx & 63;
        Qs[r * 64 + d] = Q[(size_t)(q0 + r) * E + col0 + d];
    }

    float m_run[4], l_run[4], o[4][4];
#pragma unroll
    for (int i = 0; i < 4; i++) {
        m_run[i] = -1e30f;
        l_run[i] = 0.0f;
#pragma unroll
        for (int j = 0; j < 4; j++) o[i][j] = 0.0f;
    }
    const float scale = 0.125f;   // 1/sqrt(64)

    __syncthreads();

    for (int kt = 0; kt < SEQ / 64; kt++) {
        int k0 = b * SEQ + kt * 64;
#pragma unroll
        for (int i = 0; i < 16; i++) {
            int idx = i * 256 + tid;
            int r = idx >> 6, d = idx & 63;
            Ks[r * 65 + d] = Kg[(size_t)(k0 + r) * E + col0 + d];
            Vs[r * 64 + d] = V[(size_t)(k0 + r) * E + col0 + d];
        }
        __syncthreads();

        // S = Q @ K^T  (4x4 per thread)
        float s[4][4] = {};
#pragma unroll 4
        for (int d = 0; d < 64; d++) {
            float qv[4], kv[4];
#pragma unroll
            for (int i = 0; i < 4; i++) qv[i] = Qs[(ty * 4 + i) * 64 + d];
#pragma unroll
            for (int j = 0; j < 4; j++) kv[j] = Ks[(tx * 4 + j) * 65 + d];
#pragma unroll
            for (int i = 0; i < 4; i++)
#pragma unroll
                for (int j = 0; j < 4; j++)
                    s[i][j] += qv[i] * kv[j];
        }

        // Online softmax. Lanes 0-15 / 16-31 of each warp share the same 4 rows.
#pragma unroll
        for (int i = 0; i < 4; i++) {
            float rmax = -1e30f;
#pragma unroll
            for (int j = 0; j < 4; j++) {
                s[i][j] *= scale;
                rmax = fmaxf(rmax, s[i][j]);
            }
#pragma unroll
            for (int off = 8; off > 0; off >>= 1)
                rmax = fmaxf(rmax, __shfl_xor_sync(0xffffffffu, rmax, off));
            float mnew = fmaxf(m_run[i], rmax);
            float alpha = __expf(m_run[i] - mnew);
            float ps = 0.0f;
#pragma unroll
            for (int j = 0; j < 4; j++) {
                s[i][j] = __expf(s[i][j] - mnew);
                ps += s[i][j];
            }
#pragma unroll
            for (int off = 8; off > 0; off >>= 1)
                ps += __shfl_xor_sync(0xffffffffu, ps, off);
            l_run[i] = l_run[i] * alpha + ps;
            m_run[i] = mnew;
#pragma unroll
            for (int j = 0; j < 4; j++) o[i][j] *= alpha;
        }

        __syncthreads();   // all threads done reading Ks
#pragma unroll
        for (int i = 0; i < 4; i++)
#pragma unroll
            for (int j = 0; j < 4; j++)
                Ks[(ty * 4 + i) * 65 + tx * 4 + j] = s[i][j];   // P tile
        __syncthreads();

        // O += P @ V
#pragma unroll 4
        for (int kc = 0; kc < 64; kc++) {
            float pv[4];
#pragma unroll
            for (int i = 0; i < 4; i++) pv[i] = Ks[(ty * 4 + i) * 65 + kc];
            float4 v4 = *(const float4*)&Vs[kc * 64 + tx * 4];
            float vv[4] = {v4.x, v4.y, v4.z, v4.w};
#pragma unroll
            for (int i = 0; i < 4; i++)
#pragma unroll
                for (int j = 0; j < 4; j++)
                    o[i][j] += pv[i] * vv[j];
        }
        __syncthreads();   // before next tile overwrites Ks/Vs
    }

#pragma unroll
    for (int i = 0; i < 4; i++) {
        float inv = 1.0f / l_run[i];
        int r = q0 + ty * 4 + i;
#pragma unroll
        for (int j = 0; j < 4; j++)
            Og[(size_t)r * E + col0 + tx * 4 + j] = o[i][j] * inv;
    }
}

// ---------------------------------------------------------------------------
extern "C" void kernel_launch(void* const* d_in, const int* in_sizes, int n_in,
                              void* d_out, int out_size) {
    (void)in_sizes; (void)n_in; (void)out_size;
    const float* x  = (const float*)d_in[0];
    const float* Wq = (const float*)d_in[1];
    const float* bq = (const float*)d_in[2];
    const float* Wk = (const float*)d_in[3];
    const float* bk = (const float*)d_in[4];
    const float* Wv = (const float*)d_in[5];
    const float* bv = (const float*)d_in[6];
    const float* Wo = (const float*)d_in[7];
    const float* bo = (const float*)d_in[8];
    float* out = (float*)d_out;

    float *q, *k, *v, *att;
    cudaGetSymbolAddress((void**)&q, g_q);
    cudaGetSymbolAddress((void**)&k, g_k);
    cudaGetSymbolAddress((void**)&v, g_v);
    cudaGetSymbolAddress((void**)&att, g_att);

    cudaFuncSetAttribute(attn_kernel,
                         cudaFuncAttributeMaxDynamicSharedMemorySize, ATT_SMEM);

    dim3 ggrid(E / 64, MTOT / 64);   // (16, 64)
    gemm_bias_kernel<<<ggrid, 256>>>(x, Wq, bq, q);
    gemm_bias_kernel<<<ggrid, 256>>>(x, Wk, bk, k);
    gemm_bias_kernel<<<ggrid, 256>>>(x, Wv, bv, v);

    dim3 agrid(SEQ / 64, H, BATCH);  // (32, 16, 2)
    attn_kernel<<<agrid, 256, ATT_SMEM>>>(q, k, v, att);

    gemm_bias_kernel<<<ggrid, 256>>>(att, Wo, bo, out);
}

// round 7
// speedup vs baseline: 1.3852x; 1.3852x over previous
#include <cuda_runtime.h>
#include <cstdint>

#define E 1024
#define H 16
#define DH 64
#define SEQ 2048
#define BATCH 2
#define MTOT (BATCH * SEQ)   // 4096

// Scratch (no cudaMalloc allowed).
__device__ float g_q[MTOT * E];
__device__ float g_k[MTOT * E];
__device__ float g_v[MTOT * E];
__device__ float g_att[MTOT * E];
__device__ float g_wt[4][E * E];   // transposed weights

__device__ __forceinline__ uint32_t f2tf32(float f) {
    uint32_t r;
    asm("cvt.rna.tf32.f32 %0, %1;" : "=r"(r) : "f"(f));
    return r;
}

// ---------------------------------------------------------------------------
// Weight transpose: out[n][k] = in[k][n], 1024x1024
// ---------------------------------------------------------------------------
__global__ __launch_bounds__(256) void transpose1k(const float* __restrict__ in,
                                                   float* __restrict__ out) {
    __shared__ float t[32][33];
    int bx = blockIdx.x * 32, by = blockIdx.y * 32;
    int tx = threadIdx.x, ty = threadIdx.y;
#pragma unroll
    for (int i = 0; i < 32; i += 8)
        t[ty + i][tx] = in[(size_t)(by + ty + i) * E + bx + tx];
    __syncthreads();
#pragma unroll
    for (int i = 0; i < 32; i += 8)
        out[(size_t)(bx + ty + i) * E + by + tx] = t[tx][ty + i];
}

// ---------------------------------------------------------------------------
// mma.sync tf32 GEMM: C[M,N] = A[M,K] @ Bt[N,K]^T + bias
// M=4096, N=K=1024. CTA tile 128x64, BK=32, 256 threads.
// Warp tile 32x32 = 2(M) x 4(N) m16n8k8 tiles. Warps: 4 in M x 2 in N.
// ---------------------------------------------------------------------------
#define GM 128
#define GN 64
#define GK 32
#define NSTAGE (E / GK)   // 32

__device__ __forceinline__ void mma_tf32(float c[4], const uint32_t a[4],
                                         const uint32_t b[2]) {
    asm volatile(
        "mma.sync.aligned.m16n8k8.row.col.f32.tf32.tf32.f32 "
        "{%0,%1,%2,%3}, {%4,%5,%6,%7}, {%8,%9}, {%0,%1,%2,%3};"
        : "+f"(c[0]), "+f"(c[1]), "+f"(c[2]), "+f"(c[3])
        : "r"(a[0]), "r"(a[1]), "r"(a[2]), "r"(a[3]), "r"(b[0]), "r"(b[1]));
}

__global__ __launch_bounds__(256) void gemm_tf32_kernel(
    const float* __restrict__ A, const float* __restrict__ Bt,
    const float* __restrict__ bias, float* __restrict__ C) {
    __shared__ __align__(16) float As[128][36];   // [m][k], stride 36: conflict-free frags
    __shared__ __align__(16) float Bs[64][36];    // [n][k]

    int tid = threadIdx.x;
    int lane = tid & 31, wid = tid >> 5;
    int gid = lane >> 2, tig = lane & 3;
    int m0 = blockIdx.y * GM, n0 = blockIdx.x * GN;
    int wm = (wid >> 1) * 32;   // warp row offset in tile
    int wn = (wid & 1) * 32;    // warp col offset in tile

    float4 ra[4];
    float4 rb[2];

    auto LOADG = [&](int s) {
        const float* Ap = A + (size_t)m0 * E + s * GK;
        const float* Bp = Bt + (size_t)n0 * E + s * GK;
#pragma unroll
        for (int i = 0; i < 4; i++) {
            int idx = i * 256 + tid;        // 0..1023 -> 128 rows x 8 float4
            int r = idx >> 3, f = idx & 7;
            ra[i] = *(const float4*)(Ap + (size_t)r * E + f * 4);
        }
#pragma unroll
        for (int i = 0; i < 2; i++) {
            int idx = i * 256 + tid;        // 0..511 -> 64 rows x 8 float4
            int r = idx >> 3, f = idx & 7;
            rb[i] = *(const float4*)(Bp + (size_t)r * E + f * 4);
        }
    };
    auto STORES = [&]() {
#pragma unroll
        for (int i = 0; i < 4; i++) {
            int idx = i * 256 + tid;
            int r = idx >> 3, f = idx & 7;
            uint32_t* p = (uint32_t*)&As[r][f * 4];
            p[0] = f2tf32(ra[i].x); p[1] = f2tf32(ra[i].y);
            p[2] = f2tf32(ra[i].z); p[3] = f2tf32(ra[i].w);
        }
#pragma unroll
        for (int i = 0; i < 2; i++) {
            int idx = i * 256 + tid;
            int r = idx >> 3, f = idx & 7;
            uint32_t* p = (uint32_t*)&Bs[r][f * 4];
            p[0] = f2tf32(rb[i].x); p[1] = f2tf32(rb[i].y);
            p[2] = f2tf32(rb[i].z); p[3] = f2tf32(rb[i].w);
        }
    };

    float acc[2][4][4];
#pragma unroll
    for (int mi = 0; mi < 2; mi++)
#pragma unroll
        for (int nj = 0; nj < 4; nj++)
#pragma unroll
            for (int j = 0; j < 4; j++) acc[mi][nj][j] = 0.0f;

    LOADG(0);
    STORES();
    __syncthreads();

    for (int s = 0; s < NSTAGE; s++) {
        if (s + 1 < NSTAGE) LOADG(s + 1);   // global loads in flight during compute

#pragma unroll
        for (int kk = 0; kk < 4; kk++) {
            int k = kk * 8;
            uint32_t af[2][4], bf[4][2];
#pragma unroll
            for (int mi = 0; mi < 2; mi++) {
                int r = wm + mi * 16 + gid;
                af[mi][0] = __float_as_uint(As[r][k + tig]);
                af[mi][1] = __float_as_uint(As[r + 8][k + tig]);
                af[mi][2] = __float_as_uint(As[r][k + tig + 4]);
                af[mi][3] = __float_as_uint(As[r + 8][k + tig + 4]);
            }
#pragma unroll
            for (int nj = 0; nj < 4; nj++) {
                int r = wn + nj * 8 + gid;
                bf[nj][0] = __float_as_uint(Bs[r][k + tig]);
                bf[nj][1] = __float_as_uint(Bs[r][k + tig + 4]);
            }
#pragma unroll
            for (int mi = 0; mi < 2; mi++)
#pragma unroll
                for (int nj = 0; nj < 4; nj++)
                    mma_tf32(acc[mi][nj], af[mi], bf[nj]);
        }

        __syncthreads();
        if (s + 1 < NSTAGE) {
            STORES();
            __syncthreads();
        }
    }

    // Epilogue: C = acc + bias
#pragma unroll
    for (int mi = 0; mi < 2; mi++) {
        int row0 = m0 + wm + mi * 16 + gid;
#pragma unroll
        for (int nj = 0; nj < 4; nj++) {
            int col = n0 + wn + nj * 8 + 2 * tig;
            float b0 = bias[col], b1 = bias[col + 1];
            float2 v0 = { acc[mi][nj][0] + b0, acc[mi][nj][1] + b1 };
            float2 v1 = { acc[mi][nj][2] + b0, acc[mi][nj][3] + b1 };
            *(float2*)(C + (size_t)row0 * E + col) = v0;
            *(float2*)(C + (size_t)(row0 + 8) * E + col) = v1;
        }
    }
}

// ---------------------------------------------------------------------------
// Flash attention (unchanged — SIMT fp32)
// ---------------------------------------------------------------------------
#define ATT_SMEM ((64 * 64 + 64 * 65 + 64 * 64) * 4)

__global__ __launch_bounds__(256) void attn_kernel(
    const float* __restrict__ Q, const float* __restrict__ Kg,
    const float* __restrict__ V, float* __restrict__ Og) {
    extern __shared__ float sm[];
    float* Qs = sm;
    float* Ks = sm + 64 * 64;
    float* Vs = sm + 64 * 64 + 64 * 65;

    int tid = threadIdx.x;
    int tx = tid & 15, ty = tid >> 4;
    int qt = blockIdx.x;
    int h = blockIdx.y;
    int b = blockIdx.z;
    int q0 = b * SEQ + qt * 64;
    int col0 = h * DH;

#pragma unroll
    for (int i = 0; i < 16; i++) {
        int idx = i * 256 + tid;
        int r = idx >> 6, d = idx & 63;
        Qs[r * 64 + d] = Q[(size_t)(q0 + r) * E + col0 + d];
    }

    float m_run[4], l_run[4], o[4][4];
#pragma unroll
    for (int i = 0; i < 4; i++) {
        m_run[i] = -1e30f;
        l_run[i] = 0.0f;
#pragma unroll
        for (int j = 0; j < 4; j++) o[i][j] = 0.0f;
    }
    const float scale = 0.125f;

    __syncthreads();

    for (int kt = 0; kt < SEQ / 64; kt++) {
        int k0 = b * SEQ + kt * 64;
#pragma unroll
        for (int i = 0; i < 16; i++) {
            int idx = i * 256 + tid;
            int r = idx >> 6, d = idx & 63;
            Ks[r * 65 + d] = Kg[(size_t)(k0 + r) * E + col0 + d];
            Vs[r * 64 + d] = V[(size_t)(k0 + r) * E + col0 + d];
        }
        __syncthreads();

        float s[4][4] = {};
#pragma unroll 4
        for (int d = 0; d < 64; d++) {
            float qv[4], kv[4];
#pragma unroll
            for (int i = 0; i < 4; i++) qv[i] = Qs[(ty * 4 + i) * 64 + d];
#pragma unroll
            for (int j = 0; j < 4; j++) kv[j] = Ks[(tx * 4 + j) * 65 + d];
#pragma unroll
            for (int i = 0; i < 4; i++)
#pragma unroll
                for (int j = 0; j < 4; j++)
                    s[i][j] += qv[i] * kv[j];
        }

#pragma unroll
        for (int i = 0; i < 4; i++) {
            float rmax = -1e30f;
#pragma unroll
            for (int j = 0; j < 4; j++) {
                s[i][j] *= scale;
                rmax = fmaxf(rmax, s[i][j]);
            }
#pragma unroll
            for (int off = 8; off > 0; off >>= 1)
                rmax = fmaxf(rmax, __shfl_xor_sync(0xffffffffu, rmax, off));
            float mnew = fmaxf(m_run[i], rmax);
            float alpha = __expf(m_run[i] - mnew);
            float ps = 0.0f;
#pragma unroll
            for (int j = 0; j < 4; j++) {
                s[i][j] = __expf(s[i][j] - mnew);
                ps += s[i][j];
            }
#pragma unroll
            for (int off = 8; off > 0; off >>= 1)
                ps += __shfl_xor_sync(0xffffffffu, ps, off);
            l_run[i] = l_run[i] * alpha + ps;
            m_run[i] = mnew;
#pragma unroll
            for (int j = 0; j < 4; j++) o[i][j] *= alpha;
        }

        __syncthreads();
#pragma unroll
        for (int i = 0; i < 4; i++)
#pragma unroll
            for (int j = 0; j < 4; j++)
                Ks[(ty * 4 + i) * 65 + tx * 4 + j] = s[i][j];
        __syncthreads();

#pragma unroll 4
        for (int kc = 0; kc < 64; kc++) {
            float pv[4];
#pragma unroll
            for (int i = 0; i < 4; i++) pv[i] = Ks[(ty * 4 + i) * 65 + kc];
            float4 v4 = *(const float4*)&Vs[kc * 64 + tx * 4];
            float vv[4] = {v4.x, v4.y, v4.z, v4.w};
#pragma unroll
            for (int i = 0; i < 4; i++)
#pragma unroll
                for (int j = 0; j < 4; j++)
                    o[i][j] += pv[i] * vv[j];
        }
        __syncthreads();
    }

#pragma unroll
    for (int i = 0; i < 4; i++) {
        float inv = 1.0f / l_run[i];
        int r = q0 + ty * 4 + i;
#pragma unroll
        for (int j = 0; j < 4; j++)
            Og[(size_t)r * E + col0 + tx * 4 + j] = o[i][j] * inv;
    }
}

// ---------------------------------------------------------------------------
extern "C" void kernel_launch(void* const* d_in, const int* in_sizes, int n_in,
                              void* d_out, int out_size) {
    (void)in_sizes; (void)n_in; (void)out_size;
    const float* x  = (const float*)d_in[0];
    const float* Wq = (const float*)d_in[1];
    const float* bq = (const float*)d_in[2];
    const float* Wk = (const float*)d_in[3];
    const float* bk = (const float*)d_in[4];
    const float* Wv = (const float*)d_in[5];
    const float* bv = (const float*)d_in[6];
    const float* Wo = (const float*)d_in[7];
    const float* bo = (const float*)d_in[8];
    float* out = (float*)d_out;

    float *q, *k, *v, *att, *wt;
    cudaGetSymbolAddress((void**)&q, g_q);
    cudaGetSymbolAddress((void**)&k, g_k);
    cudaGetSymbolAddress((void**)&v, g_v);
    cudaGetSymbolAddress((void**)&att, g_att);
    cudaGetSymbolAddress((void**)&wt, g_wt);
    float* wtq = wt;
    float* wtk = wt + (size_t)E * E;
    float* wtv = wt + 2 * (size_t)E * E;
    float* wto = wt + 3 * (size_t)E * E;

    cudaFuncSetAttribute(attn_kernel,
                         cudaFuncAttributeMaxDynamicSharedMemorySize, ATT_SMEM);

    dim3 tgrid(32, 32), tblk(32, 8);
    transpose1k<<<tgrid, tblk>>>(Wq, wtq);
    transpose1k<<<tgrid, tblk>>>(Wk, wtk);
    transpose1k<<<tgrid, tblk>>>(Wv, wtv);
    transpose1k<<<tgrid, tblk>>>(Wo, wto);

    dim3 ggrid(E / GN, MTOT / GM);   // (16, 32) = 512 CTAs
    gemm_tf32_kernel<<<ggrid, 256>>>(x, wtq, bq, q);
    gemm_tf32_kernel<<<ggrid, 256>>>(x, wtk, bk, k);
    gemm_tf32_kernel<<<ggrid, 256>>>(x, wtv, bv, v);

    dim3 agrid(SEQ / 64, H, BATCH);  // (32, 16, 2)
    attn_kernel<<<agrid, 256, ATT_SMEM>>>(q, k, v, att);

    gemm_tf32_kernel<<<ggrid, 256>>>(att, wto, bo, out);
}

// round 8
// speedup vs baseline: 1.4856x; 1.0725x over previous
#include <cuda_runtime.h>
#include <cstdint>

#define E 1024
#define H 16
#define DH 64
#define SEQ 2048
#define BATCH 2
#define MTOT (BATCH * SEQ)   // 4096

// Scratch (no cudaMalloc allowed).
__device__ float g_q[MTOT * E];
__device__ float g_k[MTOT * E];
__device__ float g_v[MTOT * E];
__device__ float g_att[MTOT * E];
__device__ float g_wt[4][E * E];   // transposed weights

__device__ __forceinline__ uint32_t f2tf32(float f) {
    uint32_t r;
    asm("cvt.rna.tf32.f32 %0, %1;" : "=r"(r) : "f"(f));
    return r;
}

// ---- packed f32x2 helpers (Blackwell) ----
__device__ __forceinline__ unsigned long long pk2(float x) {
    unsigned long long r;
    asm("mov.b64 %0, {%1, %1};" : "=l"(r) : "f"(x));
    return r;
}
__device__ __forceinline__ unsigned long long fma2(unsigned long long a,
                                                   unsigned long long b,
                                                   unsigned long long c) {
    unsigned long long d;
    asm("fma.rn.f32x2 %0, %1, %2, %3;" : "=l"(d) : "l"(a), "l"(b), "l"(c));
    return d;
}
__device__ __forceinline__ unsigned long long mul2(unsigned long long a,
                                                   unsigned long long b) {
    unsigned long long d;
    asm("mul.rn.f32x2 %0, %1, %2;" : "=l"(d) : "l"(a), "l"(b));
    return d;
}
__device__ __forceinline__ void upk2(unsigned long long v, float& lo, float& hi) {
    asm("mov.b64 {%0, %1}, %2;" : "=f"(lo), "=f"(hi) : "l"(v));
}

// ---------------------------------------------------------------------------
// Weight transpose: out[n][k] = in[k][n], 1024x1024
// ---------------------------------------------------------------------------
__global__ __launch_bounds__(256) void transpose1k(const float* __restrict__ in,
                                                   float* __restrict__ out) {
    __shared__ float t[32][33];
    int bx = blockIdx.x * 32, by = blockIdx.y * 32;
    int tx = threadIdx.x, ty = threadIdx.y;
#pragma unroll
    for (int i = 0; i < 32; i += 8)
        t[ty + i][tx] = in[(size_t)(by + ty + i) * E + bx + tx];
    __syncthreads();
#pragma unroll
    for (int i = 0; i < 32; i += 8)
        out[(size_t)(bx + ty + i) * E + by + tx] = t[tx][ty + i];
}

// ---------------------------------------------------------------------------
// mma.sync tf32 GEMM: C[M,N] = A[M,K] @ Bt[N,K]^T + bias   (unchanged, WIN R7)
// ---------------------------------------------------------------------------
#define GM 128
#define GN 64
#define GK 32
#define NSTAGE (E / GK)   // 32

__device__ __forceinline__ void mma_tf32(float c[4], const uint32_t a[4],
                                         const uint32_t b[2]) {
    asm volatile(
        "mma.sync.aligned.m16n8k8.row.col.f32.tf32.tf32.f32 "
        "{%0,%1,%2,%3}, {%4,%5,%6,%7}, {%8,%9}, {%0,%1,%2,%3};"
        : "+f"(c[0]), "+f"(c[1]), "+f"(c[2]), "+f"(c[3])
        : "r"(a[0]), "r"(a[1]), "r"(a[2]), "r"(a[3]), "r"(b[0]), "r"(b[1]));
}

__global__ __launch_bounds__(256) void gemm_tf32_kernel(
    const float* __restrict__ A, const float* __restrict__ Bt,
    const float* __restrict__ bias, float* __restrict__ C) {
    __shared__ __align__(16) float As[128][36];
    __shared__ __align__(16) float Bs[64][36];

    int tid = threadIdx.x;
    int lane = tid & 31, wid = tid >> 5;
    int gid = lane >> 2, tig = lane & 3;
    int m0 = blockIdx.y * GM, n0 = blockIdx.x * GN;
    int wm = (wid >> 1) * 32;
    int wn = (wid & 1) * 32;

    float4 ra[4];
    float4 rb[2];

    auto LOADG = [&](int s) {
        const float* Ap = A + (size_t)m0 * E + s * GK;
        const float* Bp = Bt + (size_t)n0 * E + s * GK;
#pragma unroll
        for (int i = 0; i < 4; i++) {
            int idx = i * 256 + tid;
            int r = idx >> 3, f = idx & 7;
            ra[i] = *(const float4*)(Ap + (size_t)r * E + f * 4);
        }
#pragma unroll
        for (int i = 0; i < 2; i++) {
            int idx = i * 256 + tid;
            int r = idx >> 3, f = idx & 7;
            rb[i] = *(const float4*)(Bp + (size_t)r * E + f * 4);
        }
    };
    auto STORES = [&]() {
#pragma unroll
        for (int i = 0; i < 4; i++) {
            int idx = i * 256 + tid;
            int r = idx >> 3, f = idx & 7;
            uint32_t* p = (uint32_t*)&As[r][f * 4];
            p[0] = f2tf32(ra[i].x); p[1] = f2tf32(ra[i].y);
            p[2] = f2tf32(ra[i].z); p[3] = f2tf32(ra[i].w);
        }
#pragma unroll
        for (int i = 0; i < 2; i++) {
            int idx = i * 256 + tid;
            int r = idx >> 3, f = idx & 7;
            uint32_t* p = (uint32_t*)&Bs[r][f * 4];
            p[0] = f2tf32(rb[i].x); p[1] = f2tf32(rb[i].y);
            p[2] = f2tf32(rb[i].z); p[3] = f2tf32(rb[i].w);
        }
    };

    float acc[2][4][4];
#pragma unroll
    for (int mi = 0; mi < 2; mi++)
#pragma unroll
        for (int nj = 0; nj < 4; nj++)
#pragma unroll
            for (int j = 0; j < 4; j++) acc[mi][nj][j] = 0.0f;

    LOADG(0);
    STORES();
    __syncthreads();

    for (int s = 0; s < NSTAGE; s++) {
        if (s + 1 < NSTAGE) LOADG(s + 1);

#pragma unroll
        for (int kk = 0; kk < 4; kk++) {
            int k = kk * 8;
            uint32_t af[2][4], bf[4][2];
#pragma unroll
            for (int mi = 0; mi < 2; mi++) {
                int r = wm + mi * 16 + gid;
                af[mi][0] = __float_as_uint(As[r][k + tig]);
                af[mi][1] = __float_as_uint(As[r + 8][k + tig]);
                af[mi][2] = __float_as_uint(As[r][k + tig + 4]);
                af[mi][3] = __float_as_uint(As[r + 8][k + tig + 4]);
            }
#pragma unroll
            for (int nj = 0; nj < 4; nj++) {
                int r = wn + nj * 8 + gid;
                bf[nj][0] = __float_as_uint(Bs[r][k + tig]);
                bf[nj][1] = __float_as_uint(Bs[r][k + tig + 4]);
            }
#pragma unroll
            for (int mi = 0; mi < 2; mi++)
#pragma unroll
                for (int nj = 0; nj < 4; nj++)
                    mma_tf32(acc[mi][nj], af[mi], bf[nj]);
        }

        __syncthreads();
        if (s + 1 < NSTAGE) {
            STORES();
            __syncthreads();
        }
    }

#pragma unroll
    for (int mi = 0; mi < 2; mi++) {
        int row0 = m0 + wm + mi * 16 + gid;
#pragma unroll
        for (int nj = 0; nj < 4; nj++) {
            int col = n0 + wn + nj * 8 + 2 * tig;
            float b0 = bias[col], b1 = bias[col + 1];
            float2 v0 = { acc[mi][nj][0] + b0, acc[mi][nj][1] + b1 };
            float2 v1 = { acc[mi][nj][2] + b0, acc[mi][nj][3] + b1 };
            *(float2*)(C + (size_t)row0 * E + col) = v0;
            *(float2*)(C + (size_t)(row0 + 8) * E + col) = v1;
        }
    }
}

// ---------------------------------------------------------------------------
// Flash attention with packed f32x2 FMAs (exact fp32 numerics).
// Smem: Qs[64][64] (pre-scaled), KT[64][66] d-major, Vs[64][64], Ps[64][65].
// ---------------------------------------------------------------------------
#define QS_OFF 0
#define KT_OFF (64 * 64)
#define VS_OFF (KT_OFF + 64 * 66)
#define PS_OFF (VS_OFF + 64 * 64)
#define ATT_SMEM ((PS_OFF + 64 * 65) * 4)

__global__ __launch_bounds__(256) void attn_kernel(
    const float* __restrict__ Q, const float* __restrict__ Kg,
    const float* __restrict__ V, float* __restrict__ Og) {
    extern __shared__ float sm[];
    float* Qs = sm + QS_OFF;
    float* KT = sm + KT_OFF;   // [d][krow], stride 66
    float* Vs = sm + VS_OFF;   // [krow][d], stride 64
    float* Ps = sm + PS_OFF;   // [qrow][kcol], stride 65

    int tid = threadIdx.x;
    int tx = tid & 15, ty = tid >> 4;
    int qt = blockIdx.x;
    int h = blockIdx.y;
    int b = blockIdx.z;
    int q0 = b * SEQ + qt * 64;
    int col0 = h * DH;

    // Load Q tile pre-scaled by 1/sqrt(Dh)
#pragma unroll
    for (int i = 0; i < 16; i++) {
        int idx = i * 256 + tid;
        int r = idx >> 6, d = idx & 63;
        Qs[r * 64 + d] = 0.125f * Q[(size_t)(q0 + r) * E + col0 + d];
    }

    float m_run[4], l_run[4];
    unsigned long long o2[4][2];
#pragma unroll
    for (int i = 0; i < 4; i++) {
        m_run[i] = -1e30f;
        l_run[i] = 0.0f;
        o2[i][0] = 0ull;
        o2[i][1] = 0ull;
    }

    __syncthreads();

    for (int kt = 0; kt < SEQ / 64; kt++) {
        int k0 = b * SEQ + kt * 64;
#pragma unroll
        for (int i = 0; i < 16; i++) {
            int idx = i * 256 + tid;
            int r = idx >> 6, d = idx & 63;
            KT[d * 66 + r] = Kg[(size_t)(k0 + r) * E + col0 + d];
            Vs[r * 64 + d] = V[(size_t)(k0 + r) * E + col0 + d];
        }
        __syncthreads();

        // S = Qs @ K^T   (packed over key-column pairs)
        unsigned long long s2[4][2] = {{0ull, 0ull}, {0ull, 0ull},
                                       {0ull, 0ull}, {0ull, 0ull}};
#pragma unroll 4
        for (int d = 0; d < 64; d++) {
            unsigned long long qq[4], kv[2];
#pragma unroll
            for (int i = 0; i < 4; i++) qq[i] = pk2(Qs[(ty * 4 + i) * 64 + d]);
#pragma unroll
            for (int j2 = 0; j2 < 2; j2++)
                kv[j2] = *(const unsigned long long*)(KT + d * 66 + tx * 4 + 2 * j2);
#pragma unroll
            for (int i = 0; i < 4; i++)
#pragma unroll
                for (int j2 = 0; j2 < 2; j2++)
                    s2[i][j2] = fma2(qq[i], kv[j2], s2[i][j2]);
        }

        float s[4][4];
#pragma unroll
        for (int i = 0; i < 4; i++) {
            upk2(s2[i][0], s[i][0], s[i][1]);
            upk2(s2[i][1], s[i][2], s[i][3]);
        }

        // Online softmax (scale already folded into Q)
#pragma unroll
        for (int i = 0; i < 4; i++) {
            float rmax = fmaxf(fmaxf(s[i][0], s[i][1]), fmaxf(s[i][2], s[i][3]));
#pragma unroll
            for (int off = 8; off > 0; off >>= 1)
                rmax = fmaxf(rmax, __shfl_xor_sync(0xffffffffu, rmax, off));
            float mnew = fmaxf(m_run[i], rmax);
            float alpha = __expf(m_run[i] - mnew);
            float ps = 0.0f;
#pragma unroll
            for (int j = 0; j < 4; j++) {
                s[i][j] = __expf(s[i][j] - mnew);
                ps += s[i][j];
            }
#pragma unroll
            for (int off = 8; off > 0; off >>= 1)
                ps += __shfl_xor_sync(0xffffffffu, ps, off);
            l_run[i] = l_run[i] * alpha + ps;
            m_run[i] = mnew;
            unsigned long long aa = pk2(alpha);
            o2[i][0] = mul2(o2[i][0], aa);
            o2[i][1] = mul2(o2[i][1], aa);
        }

        // Write P tile
#pragma unroll
        for (int i = 0; i < 4; i++)
#pragma unroll
            for (int j = 0; j < 4; j++)
                Ps[(ty * 4 + i) * 65 + tx * 4 + j] = s[i][j];
        __syncthreads();

        // O += P @ V   (packed over V-column pairs)
#pragma unroll 4
        for (int kc = 0; kc < 64; kc++) {
            unsigned long long pp[4], vv[2];
#pragma unroll
            for (int i = 0; i < 4; i++) pp[i] = pk2(Ps[(ty * 4 + i) * 65 + kc]);
#pragma unroll
            for (int j2 = 0; j2 < 2; j2++)
                vv[j2] = *(const unsigned long long*)(Vs + kc * 64 + tx * 4 + 2 * j2);
#pragma unroll
            for (int i = 0; i < 4; i++)
#pragma unroll
                for (int j2 = 0; j2 < 2; j2++)
                    o2[i][j2] = fma2(pp[i], vv[j2], o2[i][j2]);
        }
        __syncthreads();   // protect KT/Vs/Ps before next tile
    }

#pragma unroll
    for (int i = 0; i < 4; i++) {
        float inv = 1.0f / l_run[i];
        int r = q0 + ty * 4 + i;
#pragma unroll
        for (int j2 = 0; j2 < 2; j2++) {
            float lo, hi;
            upk2(o2[i][j2], lo, hi);
            float2 w = { lo * inv, hi * inv };
            *(float2*)(Og + (size_t)r * E + col0 + tx * 4 + 2 * j2) = w;
        }
    }
}

// ---------------------------------------------------------------------------
extern "C" void kernel_launch(void* const* d_in, const int* in_sizes, int n_in,
                              void* d_out, int out_size) {
    (void)in_sizes; (void)n_in; (void)out_size;
    const float* x  = (const float*)d_in[0];
    const float* Wq = (const float*)d_in[1];
    const float* bq = (const float*)d_in[2];
    const float* Wk = (const float*)d_in[3];
    const float* bk = (const float*)d_in[4];
    const float* Wv = (const float*)d_in[5];
    const float* bv = (const float*)d_in[6];
    const float* Wo = (const float*)d_in[7];
    const float* bo = (const float*)d_in[8];
    float* out = (float*)d_out;

    float *q, *k, *v, *att, *wt;
    cudaGetSymbolAddress((void**)&q, g_q);
    cudaGetSymbolAddress((void**)&k, g_k);
    cudaGetSymbolAddress((void**)&v, g_v);
    cudaGetSymbolAddress((void**)&att, g_att);
    cudaGetSymbolAddress((void**)&wt, g_wt);
    float* wtq = wt;
    float* wtk = wt + (size_t)E * E;
    float* wtv = wt + 2 * (size_t)E * E;
    float* wto = wt + 3 * (size_t)E * E;

    cudaFuncSetAttribute(attn_kernel,
                         cudaFuncAttributeMaxDynamicSharedMemorySize, ATT_SMEM);

    dim3 tgrid(32, 32), tblk(32, 8);
    transpose1k<<<tgrid, tblk>>>(Wq, wtq);
    transpose1k<<<tgrid, tblk>>>(Wk, wtk);
    transpose1k<<<tgrid, tblk>>>(Wv, wtv);
    transpose1k<<<tgrid, tblk>>>(Wo, wto);

    dim3 ggrid(E / GN, MTOT / GM);   // (16, 32) = 512 CTAs
    gemm_tf32_kernel<<<ggrid, 256>>>(x, wtq, bq, q);
    gemm_tf32_kernel<<<ggrid, 256>>>(x, wtk, bk, k);
    gemm_tf32_kernel<<<ggrid, 256>>>(x, wtv, bv, v);

    dim3 agrid(SEQ / 64, H, BATCH);  // (32, 16, 2)
    attn_kernel<<<agrid, 256, ATT_SMEM>>>(q, k, v, att);

    gemm_tf32_kernel<<<ggrid, 256>>>(att, wto, bo, out);
}

// round 10
// speedup vs baseline: 1.6391x; 1.1033x over previous
#include <cuda_runtime.h>
#include <cstdint>

#define E 1024
#define H 16
#define DH 64
#define SEQ 2048
#define BATCH 2
#define MTOT (BATCH * SEQ)   // 4096

// Scratch (no cudaMalloc allowed).
__device__ float g_q[MTOT * E];
__device__ float g_k[MTOT * E];
__device__ float g_v[MTOT * E];
__device__ float g_att[MTOT * E];
__device__ float g_wt[4][E * E];   // transposed weights

__device__ __forceinline__ uint32_t f2tf32(float f) {
    uint32_t r;
    asm("cvt.rna.tf32.f32 %0, %1;" : "=r"(r) : "f"(f));
    return r;
}

// ---- packed f32x2 helpers (Blackwell) ----
__device__ __forceinline__ unsigned long long pk2(float x) {
    unsigned long long r;
    asm("mov.b64 %0, {%1, %1};" : "=l"(r) : "f"(x));
    return r;
}
__device__ __forceinline__ unsigned long long fma2(unsigned long long a,
                                                   unsigned long long b,
                                                   unsigned long long c) {
    unsigned long long d;
    asm("fma.rn.f32x2 %0, %1, %2, %3;" : "=l"(d) : "l"(a), "l"(b), "l"(c));
    return d;
}
__device__ __forceinline__ unsigned long long mul2(unsigned long long a,
                                                   unsigned long long b) {
    unsigned long long d;
    asm("mul.rn.f32x2 %0, %1, %2;" : "=l"(d) : "l"(a), "l"(b));
    return d;
}
__device__ __forceinline__ void upk2(unsigned long long v, float& lo, float& hi) {
    asm("mov.b64 {%0, %1}, %2;" : "=f"(lo), "=f"(hi) : "l"(v));
}

// ---------------------------------------------------------------------------
// Weight transpose: out[n][k] = in[k][n], 1024x1024
// ---------------------------------------------------------------------------
__global__ __launch_bounds__(256) void transpose1k(const float* __restrict__ in,
                                                   float* __restrict__ out) {
    __shared__ float t[32][33];
    int bx = blockIdx.x * 32, by = blockIdx.y * 32;
    int tx = threadIdx.x, ty = threadIdx.y;
#pragma unroll
    for (int i = 0; i < 32; i += 8)
        t[ty + i][tx] = in[(size_t)(by + ty + i) * E + bx + tx];
    __syncthreads();
#pragma unroll
    for (int i = 0; i < 32; i += 8)
        out[(size_t)(bx + ty + i) * E + by + tx] = t[tx][ty + i];
}

// ---------------------------------------------------------------------------
// mma.sync tf32 GEMM (unchanged, WIN R7)
// ---------------------------------------------------------------------------
#define GM 128
#define GN 64
#define GK 32
#define NSTAGE (E / GK)   // 32

__device__ __forceinline__ void mma_tf32(float c[4], const uint32_t a[4],
                                         const uint32_t b[2]) {
    asm volatile(
        "mma.sync.aligned.m16n8k8.row.col.f32.tf32.tf32.f32 "
        "{%0,%1,%2,%3}, {%4,%5,%6,%7}, {%8,%9}, {%0,%1,%2,%3};"
        : "+f"(c[0]), "+f"(c[1]), "+f"(c[2]), "+f"(c[3])
        : "r"(a[0]), "r"(a[1]), "r"(a[2]), "r"(a[3]), "r"(b[0]), "r"(b[1]));
}

__global__ __launch_bounds__(256) void gemm_tf32_kernel(
    const float* __restrict__ A, const float* __restrict__ Bt,
    const float* __restrict__ bias, float* __restrict__ C) {
    __shared__ __align__(16) float As[128][36];
    __shared__ __align__(16) float Bs[64][36];

    int tid = threadIdx.x;
    int lane = tid & 31, wid = tid >> 5;
    int gid = lane >> 2, tig = lane & 3;
    int m0 = blockIdx.y * GM, n0 = blockIdx.x * GN;
    int wm = (wid >> 1) * 32;
    int wn = (wid & 1) * 32;

    float4 ra[4];
    float4 rb[2];

    auto LOADG = [&](int s) {
        const float* Ap = A + (size_t)m0 * E + s * GK;
        const float* Bp = Bt + (size_t)n0 * E + s * GK;
#pragma unroll
        for (int i = 0; i < 4; i++) {
            int idx = i * 256 + tid;
            int r = idx >> 3, f = idx & 7;
            ra[i] = *(const float4*)(Ap + (size_t)r * E + f * 4);
        }
#pragma unroll
        for (int i = 0; i < 2; i++) {
            int idx = i * 256 + tid;
            int r = idx >> 3, f = idx & 7;
            rb[i] = *(const float4*)(Bp + (size_t)r * E + f * 4);
        }
    };
    auto STORES = [&]() {
#pragma unroll
        for (int i = 0; i < 4; i++) {
            int idx = i * 256 + tid;
            int r = idx >> 3, f = idx & 7;
            uint32_t* p = (uint32_t*)&As[r][f * 4];
            p[0] = f2tf32(ra[i].x); p[1] = f2tf32(ra[i].y);
            p[2] = f2tf32(ra[i].z); p[3] = f2tf32(ra[i].w);
        }
#pragma unroll
        for (int i = 0; i < 2; i++) {
            int idx = i * 256 + tid;
            int r = idx >> 3, f = idx & 7;
            uint32_t* p = (uint32_t*)&Bs[r][f * 4];
            p[0] = f2tf32(rb[i].x); p[1] = f2tf32(rb[i].y);
            p[2] = f2tf32(rb[i].z); p[3] = f2tf32(rb[i].w);
        }
    };

    float acc[2][4][4];
#pragma unroll
    for (int mi = 0; mi < 2; mi++)
#pragma unroll
        for (int nj = 0; nj < 4; nj++)
#pragma unroll
            for (int j = 0; j < 4; j++) acc[mi][nj][j] = 0.0f;

    LOADG(0);
    STORES();
    __syncthreads();

    for (int s = 0; s < NSTAGE; s++) {
        if (s + 1 < NSTAGE) LOADG(s + 1);

#pragma unroll
        for (int kk = 0; kk < 4; kk++) {
            int k = kk * 8;
            uint32_t af[2][4], bf[4][2];
#pragma unroll
            for (int mi = 0; mi < 2; mi++) {
                int r = wm + mi * 16 + gid;
                af[mi][0] = __float_as_uint(As[r][k + tig]);
                af[mi][1] = __float_as_uint(As[r + 8][k + tig]);
                af[mi][2] = __float_as_uint(As[r][k + tig + 4]);
                af[mi][3] = __float_as_uint(As[r + 8][k + tig + 4]);
            }
#pragma unroll
            for (int nj = 0; nj < 4; nj++) {
                int r = wn + nj * 8 + gid;
                bf[nj][0] = __float_as_uint(Bs[r][k + tig]);
                bf[nj][1] = __float_as_uint(Bs[r][k + tig + 4]);
            }
#pragma unroll
            for (int mi = 0; mi < 2; mi++)
#pragma unroll
                for (int nj = 0; nj < 4; nj++)
                    mma_tf32(acc[mi][nj], af[mi], bf[nj]);
        }

        __syncthreads();
        if (s + 1 < NSTAGE) {
            STORES();
            __syncthreads();
        }
    }

#pragma unroll
    for (int mi = 0; mi < 2; mi++) {
        int row0 = m0 + wm + mi * 16 + gid;
#pragma unroll
        for (int nj = 0; nj < 4; nj++) {
            int col = n0 + wn + nj * 8 + 2 * tig;
            float b0 = bias[col], b1 = bias[col + 1];
            float2 v0 = { acc[mi][nj][0] + b0, acc[mi][nj][1] + b1 };
            float2 v1 = { acc[mi][nj][2] + b0, acc[mi][nj][3] + b1 };
            *(float2*)(C + (size_t)row0 * E + col) = v0;
            *(float2*)(C + (size_t)(row0 + 8) * E + col) = v1;
        }
    }
}

// ---------------------------------------------------------------------------
// Flash attention v3: 128q x 64k tile, 8x4 per-thread, f32x2 everywhere.
// QK packs over d (direct LDS.64 of row-major Q/K, no MOVs, no transposes);
// PV packs over output columns. All buffers natural row-major.
// Thread map: tx = tid&15, ty = tid>>4. Rows ty*8+i (i<8).
// QK keys: {tx, tx+16, tx+32, tx+48}. PV d-cols: {2tx,2tx+1,2tx+32,2tx+33}.
// ---------------------------------------------------------------------------
#define AQ_STR 66
#define AK_STR 66
#define AP_STR 66
#define AQ_OFF 0
#define AK_OFF (128 * AQ_STR)                  // 8448
#define AV_OFF (AK_OFF + 64 * AK_STR)          // + 4224
#define AP_OFF (AV_OFF + 64 * 64)              // + 4096
#define ATT_SMEM ((AP_OFF + 128 * AP_STR) * 4) // 100864 B

typedef unsigned long long u64;

__global__ __launch_bounds__(256, 2) void attn_kernel(
    const float* __restrict__ Q, const float* __restrict__ Kg,
    const float* __restrict__ V, float* __restrict__ Og) {
    extern __shared__ float sm[];
    float* Qs = sm + AQ_OFF;   // [128][66]
    float* Ks = sm + AK_OFF;   // [64][66]
    float* Vs = sm + AV_OFF;   // [64][64]
    float* Ps = sm + AP_OFF;   // [128][66]

    int tid = threadIdx.x;
    int tx = tid & 15, ty = tid >> 4;
    int qt = blockIdx.x;
    int h = blockIdx.y;
    int b = blockIdx.z;
    int q0 = b * SEQ + qt * 128;
    int col0 = h * DH;

    // Load Q tile (128x64), pre-scaled by 1/8. 8 float4 per thread.
#pragma unroll
    for (int i = 0; i < 8; i++) {
        int idx = i * 256 + tid;          // 0..2047 -> 128 rows x 16 float4
        int r = idx >> 4, f = idx & 15;
        float4 v4 = *(const float4*)(Q + (size_t)(q0 + r) * E + col0 + f * 4);
        float* p = Qs + r * AQ_STR + f * 4;
        float2 a = { 0.125f * v4.x, 0.125f * v4.y };
        float2 c = { 0.125f * v4.z, 0.125f * v4.w };
        *(float2*)p = a;
        *(float2*)(p + 2) = c;
    }

    float m_run[8], l_run[8];
    u64 o2[8][2];
#pragma unroll
    for (int i = 0; i < 8; i++) {
        m_run[i] = -1e30f;
        l_run[i] = 0.0f;
        o2[i][0] = 0ull;
        o2[i][1] = 0ull;
    }

    __syncthreads();

    const float* qb = Qs + (ty * 8) * AQ_STR;
    float* pb = Ps + (ty * 8) * AP_STR;

    for (int kt = 0; kt < SEQ / 64; kt++) {
        int k0 = b * SEQ + kt * 64;
        // Load K (stride 66, via float2 stores) and V (stride 64, float4)
#pragma unroll
        for (int i = 0; i < 4; i++) {
            int idx = i * 256 + tid;      // 0..1023 -> 64 rows x 16 float4
            int r = idx >> 4, f = idx & 15;
            float4 k4 = *(const float4*)(Kg + (size_t)(k0 + r) * E + col0 + f * 4);
            float* kp = Ks + r * AK_STR + f * 4;
            *(float2*)kp = make_float2(k4.x, k4.y);
            *(float2*)(kp + 2) = make_float2(k4.z, k4.w);
            float4 v4 = *(const float4*)(V + (size_t)(k0 + r) * E + col0 + f * 4);
            *(float4*)(Vs + r * 64 + f * 4) = v4;
        }
        __syncthreads();

        // ---- S = Q @ K^T, packed over d ----
        u64 s2[8][4];
#pragma unroll
        for (int i = 0; i < 8; i++)
#pragma unroll
            for (int j = 0; j < 4; j++) s2[i][j] = 0ull;

#pragma unroll 4
        for (int m = 0; m < 32; m++) {
            u64 kp[4];
#pragma unroll
            for (int j = 0; j < 4; j++)
                kp[j] = *(const u64*)(Ks + (tx + 16 * j) * AK_STR + 2 * m);
#pragma unroll
            for (int i = 0; i < 8; i++) {
                u64 qp = *(const u64*)(qb + i * AQ_STR + 2 * m);
#pragma unroll
                for (int j = 0; j < 4; j++)
                    s2[i][j] = fma2(qp, kp[j], s2[i][j]);
            }
        }

        // ---- online softmax + P store ----
#pragma unroll
        for (int i = 0; i < 8; i++) {
            float s[4];
#pragma unroll
            for (int j = 0; j < 4; j++) {
                float lo, hi;
                upk2(s2[i][j], lo, hi);
                s[j] = lo + hi;
            }
            float rmax = fmaxf(fmaxf(s[0], s[1]), fmaxf(s[2], s[3]));
#pragma unroll
            for (int off = 8; off > 0; off >>= 1)
                rmax = fmaxf(rmax, __shfl_xor_sync(0xffffffffu, rmax, off));
            float mnew = fmaxf(m_run[i], rmax);
            float alpha = __expf(m_run[i] - mnew);
            float ps = 0.0f;
#pragma unroll
            for (int j = 0; j < 4; j++) {
                s[j] = __expf(s[j] - mnew);
                ps += s[j];
            }
#pragma unroll
            for (int off = 8; off > 0; off >>= 1)
                ps += __shfl_xor_sync(0xffffffffu, ps, off);
            l_run[i] = l_run[i] * alpha + ps;
            m_run[i] = mnew;
            u64 aa = pk2(alpha);
            o2[i][0] = mul2(o2[i][0], aa);
            o2[i][1] = mul2(o2[i][1], aa);
#pragma unroll
            for (int j = 0; j < 4; j++)
                pb[i * AP_STR + tx + 16 * j] = s[j];
        }
        __syncthreads();

        // ---- O += P @ V, spatial packing over output cols, 2 kc per step ----
#pragma unroll 4
        for (int m = 0; m < 32; m++) {
            int kc = 2 * m;
            u64 v0a = *(const u64*)(Vs + kc * 64 + 2 * tx);
            u64 v0b = *(const u64*)(Vs + kc * 64 + 2 * tx + 32);
            u64 v1a = *(const u64*)(Vs + (kc + 1) * 64 + 2 * tx);
            u64 v1b = *(const u64*)(Vs + (kc + 1) * 64 + 2 * tx + 32);
#pragma unroll
            for (int i = 0; i < 8; i++) {
                u64 pp = *(const u64*)(pb + i * AP_STR + kc);
                float plo, phi;
                upk2(pp, plo, phi);
                u64 p0 = pk2(plo), p1 = pk2(phi);
                o2[i][0] = fma2(p0, v0a, o2[i][0]);
                o2[i][1] = fma2(p0, v0b, o2[i][1]);
                o2[i][0] = fma2(p1, v1a, o2[i][0]);
                o2[i][1] = fma2(p1, v1b, o2[i][1]);
            }
        }
        __syncthreads();   // protect Ks/Vs/Ps before next tile
    }

#pragma unroll
    for (int i = 0; i < 8; i++) {
        float inv = 1.0f / l_run[i];
        int r = q0 + ty * 8 + i;
        float lo, hi;
        upk2(o2[i][0], lo, hi);
        *(float2*)(Og + (size_t)r * E + col0 + 2 * tx) =
            make_float2(lo * inv, hi * inv);
        upk2(o2[i][1], lo, hi);
        *(float2*)(Og + (size_t)r * E + col0 + 2 * tx + 32) =
            make_float2(lo * inv, hi * inv);
    }
}

// ---------------------------------------------------------------------------
extern "C" void kernel_launch(void* const* d_in, const int* in_sizes, int n_in,
                              void* d_out, int out_size) {
    (void)in_sizes; (void)n_in; (void)out_size;
    const float* x  = (const float*)d_in[0];
    const float* Wq = (const float*)d_in[1];
    const float* bq = (const float*)d_in[2];
    const float* Wk = (const float*)d_in[3];
    const float* bk = (const float*)d_in[4];
    const float* Wv = (const float*)d_in[5];
    const float* bv = (const float*)d_in[6];
    const float* Wo = (const float*)d_in[7];
    const float* bo = (const float*)d_in[8];
    float* out = (float*)d_out;

    float *q, *k, *v, *att, *wt;
    cudaGetSymbolAddress((void**)&q, g_q);
    cudaGetSymbolAddress((void**)&k, g_k);
    cudaGetSymbolAddress((void**)&v, g_v);
    cudaGetSymbolAddress((void**)&att, g_att);
    cudaGetSymbolAddress((void**)&wt, g_wt);
    float* wtq = wt;
    float* wtk = wt + (size_t)E * E;
    float* wtv = wt + 2 * (size_t)E * E;
    float* wto = wt + 3 * (size_t)E * E;

    cudaFuncSetAttribute(attn_kernel,
                         cudaFuncAttributeMaxDynamicSharedMemorySize, ATT_SMEM);

    dim3 tgrid(32, 32), tblk(32, 8);
    transpose1k<<<tgrid, tblk>>>(Wq, wtq);
    transpose1k<<<tgrid, tblk>>>(Wk, wtk);
    transpose1k<<<tgrid, tblk>>>(Wv, wtv);
    transpose1k<<<tgrid, tblk>>>(Wo, wto);

    dim3 ggrid(E / GN, MTOT / GM);   // (16, 32) = 512 CTAs
    gemm_tf32_kernel<<<ggrid, 256>>>(x, wtq, bq, q);
    gemm_tf32_kernel<<<ggrid, 256>>>(x, wtk, bk, k);
    gemm_tf32_kernel<<<ggrid, 256>>>(x, wtv, bv, v);

    dim3 agrid(SEQ / 128, H, BATCH);  // (16, 16, 2) = 512 CTAs
    attn_kernel<<<agrid, 256, ATT_SMEM>>>(q, k, v, att);

    gemm_tf32_kernel<<<ggrid, 256>>>(att, wto, bo, out);
}

// round 15
// speedup vs baseline: 2.8061x; 1.7120x over previous
#include <cuda_runtime.h>
#include <cstdint>

#define E 1024
#define H 16
#define DH 64
#define SEQ 2048
#define BATCH 2
#define MTOT (BATCH * SEQ)   // 4096

// Scratch (no cudaMalloc allowed).
__device__ float g_q[MTOT * E];
__device__ float g_k[MTOT * E];
__device__ float g_v[MTOT * E];
__device__ float g_att[MTOT * E];
__device__ float g_wt[4][E * E];   // transposed weights

typedef unsigned long long u64;

__device__ __forceinline__ uint32_t f2tf32(float f) {
    uint32_t r;
    asm("cvt.rna.tf32.f32 %0, %1;" : "=r"(r) : "f"(f));
    return r;
}

__device__ __forceinline__ void mma_tf32(float c[4], const uint32_t a[4],
                                         const uint32_t b[2]) {
    asm volatile(
        "mma.sync.aligned.m16n8k8.row.col.f32.tf32.tf32.f32 "
        "{%0,%1,%2,%3}, {%4,%5,%6,%7}, {%8,%9}, {%0,%1,%2,%3};"
        : "+f"(c[0]), "+f"(c[1]), "+f"(c[2]), "+f"(c[3])
        : "r"(a[0]), "r"(a[1]), "r"(a[2]), "r"(a[3]), "r"(b[0]), "r"(b[1]));
}

// ---------------------------------------------------------------------------
// Weight transpose: out[n][k] = in[k][n], 1024x1024
// ---------------------------------------------------------------------------
__global__ __launch_bounds__(256) void transpose1k(const float* __restrict__ in,
                                                   float* __restrict__ out) {
    __shared__ float t[32][33];
    int bx = blockIdx.x * 32, by = blockIdx.y * 32;
    int tx = threadIdx.x, ty = threadIdx.y;
#pragma unroll
    for (int i = 0; i < 32; i += 8)
        t[ty + i][tx] = in[(size_t)(by + ty + i) * E + bx + tx];
    __syncthreads();
#pragma unroll
    for (int i = 0; i < 32; i += 8)
        out[(size_t)(bx + ty + i) * E + by + tx] = t[tx][ty + i];
}

// ---------------------------------------------------------------------------
// mma.sync tf32 GEMM (unchanged, WIN R7)
// ---------------------------------------------------------------------------
#define GM 128
#define GN 64
#define GK 32
#define NSTAGE (E / GK)   // 32

__global__ __launch_bounds__(256) void gemm_tf32_kernel(
    const float* __restrict__ A, const float* __restrict__ Bt,
    const float* __restrict__ bias, float* __restrict__ C) {
    __shared__ __align__(16) float As[128][36];
    __shared__ __align__(16) float Bs[64][36];

    int tid = threadIdx.x;
    int lane = tid & 31, wid = tid >> 5;
    int gid = lane >> 2, tig = lane & 3;
    int m0 = blockIdx.y * GM, n0 = blockIdx.x * GN;
    int wm = (wid >> 1) * 32;
    int wn = (wid & 1) * 32;

    float4 ra[4];
    float4 rb[2];

    auto LOADG = [&](int s) {
        const float* Ap = A + (size_t)m0 * E + s * GK;
        const float* Bp = Bt + (size_t)n0 * E + s * GK;
#pragma unroll
        for (int i = 0; i < 4; i++) {
            int idx = i * 256 + tid;
            int r = idx >> 3, f = idx & 7;
            ra[i] = *(const float4*)(Ap + (size_t)r * E + f * 4);
        }
#pragma unroll
        for (int i = 0; i < 2; i++) {
            int idx = i * 256 + tid;
            int r = idx >> 3, f = idx & 7;
            rb[i] = *(const float4*)(Bp + (size_t)r * E + f * 4);
        }
    };
    auto STORES = [&]() {
#pragma unroll
        for (int i = 0; i < 4; i++) {
            int idx = i * 256 + tid;
            int r = idx >> 3, f = idx & 7;
            uint32_t* p = (uint32_t*)&As[r][f * 4];
            p[0] = f2tf32(ra[i].x); p[1] = f2tf32(ra[i].y);
            p[2] = f2tf32(ra[i].z); p[3] = f2tf32(ra[i].w);
        }
#pragma unroll
        for (int i = 0; i < 2; i++) {
            int idx = i * 256 + tid;
            int r = idx >> 3, f = idx & 7;
            uint32_t* p = (uint32_t*)&Bs[r][f * 4];
            p[0] = f2tf32(rb[i].x); p[1] = f2tf32(rb[i].y);
            p[2] = f2tf32(rb[i].z); p[3] = f2tf32(rb[i].w);
        }
    };

    float acc[2][4][4];
#pragma unroll
    for (int mi = 0; mi < 2; mi++)
#pragma unroll
        for (int nj = 0; nj < 4; nj++)
#pragma unroll
            for (int j = 0; j < 4; j++) acc[mi][nj][j] = 0.0f;

    LOADG(0);
    STORES();
    __syncthreads();

    for (int s = 0; s < NSTAGE; s++) {
        if (s + 1 < NSTAGE) LOADG(s + 1);

#pragma unroll
        for (int kk = 0; kk < 4; kk++) {
            int k = kk * 8;
            uint32_t af[2][4], bf[4][2];
#pragma unroll
            for (int mi = 0; mi < 2; mi++) {
                int r = wm + mi * 16 + gid;
                af[mi][0] = __float_as_uint(As[r][k + tig]);
                af[mi][1] = __float_as_uint(As[r + 8][k + tig]);
                af[mi][2] = __float_as_uint(As[r][k + tig + 4]);
                af[mi][3] = __float_as_uint(As[r + 8][k + tig + 4]);
            }
#pragma unroll
            for (int nj = 0; nj < 4; nj++) {
                int r = wn + nj * 8 + gid;
                bf[nj][0] = __float_as_uint(Bs[r][k + tig]);
                bf[nj][1] = __float_as_uint(Bs[r][k + tig + 4]);
            }
#pragma unroll
            for (int mi = 0; mi < 2; mi++)
#pragma unroll
                for (int nj = 0; nj < 4; nj++)
                    mma_tf32(acc[mi][nj], af[mi], bf[nj]);
        }

        __syncthreads();
        if (s + 1 < NSTAGE) {
            STORES();
            __syncthreads();
        }
    }

#pragma unroll
    for (int mi = 0; mi < 2; mi++) {
        int row0 = m0 + wm + mi * 16 + gid;
#pragma unroll
        for (int nj = 0; nj < 4; nj++) {
            int col = n0 + wn + nj * 8 + 2 * tig;
            float b0 = bias[col], b1 = bias[col + 1];
            float2 v0 = { acc[mi][nj][0] + b0, acc[mi][nj][1] + b1 };
            float2 v1 = { acc[mi][nj][2] + b0, acc[mi][nj][3] + b1 };
            *(float2*)(C + (size_t)row0 * E + col) = v0;
            *(float2*)(C + (size_t)(row0 + 8) * E + col) = v1;
        }
    }
}

// ---------------------------------------------------------------------------
// Flash attention v4: tensor-core (mma.sync tf32) QK^T and PV.
// CTA: 256 thr / 8 warps; tile 128q x 64k; warp w owns q rows [16w, 16w+16).
// Smem stride 68 (== 4 mod 32): all fragment accesses conflict-free.
// Softmax + P tile fully warp-local (rows gid / gid+8 of the warp's 16).
// ---------------------------------------------------------------------------
#define AST 68
#define AQ_OFF 0
#define AK_OFF (128 * AST)
#define AV_OFF (AK_OFF + 64 * AST)
#define AP_OFF (AV_OFF + 64 * AST)
#define ATT_SMEM ((AP_OFF + 128 * AST) * 4)   // 104448 B

__global__ __launch_bounds__(256, 2) void attn_kernel(
    const float* __restrict__ Q, const float* __restrict__ Kg,
    const float* __restrict__ V, float* __restrict__ Og) {
    extern __shared__ uint32_t smu[];
    uint32_t* Qs = smu + AQ_OFF;   // [128][68] tf32, pre-scaled
    uint32_t* Ks = smu + AK_OFF;   // [64][68]  tf32, K rows (key-major)
    uint32_t* Vt = smu + AV_OFF;   // [64][68]  tf32, V transposed (d-major)
    uint32_t* Ps = smu + AP_OFF;   // [128][68] tf32 weights

    int tid = threadIdx.x;
    int lane = tid & 31, wid = tid >> 5;
    int g = lane >> 2, t = lane & 3;
    int qt = blockIdx.x, h = blockIdx.y, b = blockIdx.z;
    int q0 = b * SEQ + qt * 128;
    int col0 = h * DH;
    int r0 = wid * 16;

    // Load Q tile (128x64), scale by 1/8, convert to tf32.
#pragma unroll
    for (int i = 0; i < 8; i++) {
        int idx = i * 256 + tid;
        int r = idx >> 4, f = idx & 15;
        float4 v4 = *(const float4*)(Q + (size_t)(q0 + r) * E + col0 + f * 4);
        uint32_t* p = Qs + r * AST + f * 4;
        p[0] = f2tf32(0.125f * v4.x);
        p[1] = f2tf32(0.125f * v4.y);
        p[2] = f2tf32(0.125f * v4.z);
        p[3] = f2tf32(0.125f * v4.w);
    }

    float mA = -1e30f, mB = -1e30f, lA = 0.0f, lB = 0.0f;
    float O[8][4];
#pragma unroll
    for (int j = 0; j < 8; j++)
#pragma unroll
        for (int c = 0; c < 4; c++) O[j][c] = 0.0f;

    __syncthreads();

    for (int kt = 0; kt < SEQ / 64; kt++) {
        int k0 = b * SEQ + kt * 64;
        // K rows (key-major) + V transposed (d-major), both tf32.
#pragma unroll
        for (int i = 0; i < 4; i++) {
            int idx = i * 256 + tid;
            int r = idx >> 4, f = idx & 15;
            float4 k4 = *(const float4*)(Kg + (size_t)(k0 + r) * E + col0 + f * 4);
            uint32_t* p = Ks + r * AST + f * 4;
            p[0] = f2tf32(k4.x); p[1] = f2tf32(k4.y);
            p[2] = f2tf32(k4.z); p[3] = f2tf32(k4.w);

            int rv = idx & 63, dv = (idx >> 6) * 4;
            float4 v4 = *(const float4*)(V + (size_t)(k0 + rv) * E + col0 + dv);
            Vt[(dv + 0) * AST + rv] = f2tf32(v4.x);
            Vt[(dv + 1) * AST + rv] = f2tf32(v4.y);
            Vt[(dv + 2) * AST + rv] = f2tf32(v4.z);
            Vt[(dv + 3) * AST + rv] = f2tf32(v4.w);
        }
        __syncthreads();

        // ---- S = Q @ K^T : 1(M) x 8(N) tiles, 8 k-steps ----
        float S[8][4];
#pragma unroll
        for (int j = 0; j < 8; j++)
#pragma unroll
            for (int c = 0; c < 4; c++) S[j][c] = 0.0f;

#pragma unroll
        for (int s = 0; s < 8; s++) {
            uint32_t a[4];
            const uint32_t* qa = Qs + (r0 + g) * AST + 8 * s + t;
            a[0] = qa[0];
            a[1] = qa[8 * AST];
            a[2] = qa[4];
            a[3] = qa[8 * AST + 4];
#pragma unroll
            for (int j = 0; j < 8; j++) {
                uint32_t bf[2];
                const uint32_t* kb = Ks + (8 * j + g) * AST + 8 * s + t;
                bf[0] = kb[0];
                bf[1] = kb[4];
                mma_tf32(S[j], a, bf);
            }
        }

        // ---- online softmax; rows A = r0+g (c0,c1), B = r0+g+8 (c2,c3) ----
        float rmaxA = -1e30f, rmaxB = -1e30f;
#pragma unroll
        for (int j = 0; j < 8; j++) {
            rmaxA = fmaxf(rmaxA, fmaxf(S[j][0], S[j][1]));
            rmaxB = fmaxf(rmaxB, fmaxf(S[j][2], S[j][3]));
        }
        rmaxA = fmaxf(rmaxA, __shfl_xor_sync(0xffffffffu, rmaxA, 1));
        rmaxA = fmaxf(rmaxA, __shfl_xor_sync(0xffffffffu, rmaxA, 2));
        rmaxB = fmaxf(rmaxB, __shfl_xor_sync(0xffffffffu, rmaxB, 1));
        rmaxB = fmaxf(rmaxB, __shfl_xor_sync(0xffffffffu, rmaxB, 2));

        float mnA = fmaxf(mA, rmaxA), mnB = fmaxf(mB, rmaxB);
        float aA = __expf(mA - mnA), aB = __expf(mB - mnB);
        float sA = 0.0f, sB = 0.0f;
#pragma unroll
        for (int j = 0; j < 8; j++) {
            S[j][0] = __expf(S[j][0] - mnA);
            S[j][1] = __expf(S[j][1] - mnA);
            sA += S[j][0] + S[j][1];
            S[j][2] = __expf(S[j][2] - mnB);
            S[j][3] = __expf(S[j][3] - mnB);
            sB += S[j][2] + S[j][3];
        }
        sA += __shfl_xor_sync(0xffffffffu, sA, 1);
        sA += __shfl_xor_sync(0xffffffffu, sA, 2);
        sB += __shfl_xor_sync(0xffffffffu, sB, 1);
        sB += __shfl_xor_sync(0xffffffffu, sB, 2);
        lA = lA * aA + sA; mA = mnA;
        lB = lB * aB + sB; mB = mnB;

#pragma unroll
        for (int j = 0; j < 8; j++) {
            O[j][0] *= aA; O[j][1] *= aA;
            O[j][2] *= aB; O[j][3] *= aB;
            // P tile (warp-private rows), tf32, packed 2-col stores
            u64 pA = (u64)f2tf32(S[j][0]) | ((u64)f2tf32(S[j][1]) << 32);
            *(u64*)(Ps + (r0 + g) * AST + 8 * j + 2 * t) = pA;
            u64 pB = (u64)f2tf32(S[j][2]) | ((u64)f2tf32(S[j][3]) << 32);
            *(u64*)(Ps + (r0 + g + 8) * AST + 8 * j + 2 * t) = pB;
        }
        __syncwarp();   // P visibility within warp before fragment reload

        // ---- O += P @ V : A = P rows, B = Vt (d-major) ----
#pragma unroll
        for (int s = 0; s < 8; s++) {
            uint32_t a[4];
            const uint32_t* pa = Ps + (r0 + g) * AST + 8 * s + t;
            a[0] = pa[0];
            a[1] = pa[8 * AST];
            a[2] = pa[4];
            a[3] = pa[8 * AST + 4];
#pragma unroll
            for (int j = 0; j < 8; j++) {
                uint32_t bf[2];
                const uint32_t* vb = Vt + (8 * j + g) * AST + 8 * s + t;
                bf[0] = vb[0];
                bf[1] = vb[4];
                mma_tf32(O[j], a, bf);
            }
        }
        __syncthreads();   // protect Ks/Vt before next tile load
    }

    float iA = 1.0f / lA, iB = 1.0f / lB;
#pragma unroll
    for (int j = 0; j < 8; j++) {
        *(float2*)(Og + (size_t)(q0 + r0 + g) * E + col0 + 8 * j + 2 * t) =
            make_float2(O[j][0] * iA, O[j][1] * iA);
        *(float2*)(Og + (size_t)(q0 + r0 + g + 8) * E + col0 + 8 * j + 2 * t) =
            make_float2(O[j][2] * iB, O[j][3] * iB);
    }
}

// ---------------------------------------------------------------------------
extern "C" void kernel_launch(void* const* d_in, const int* in_sizes, int n_in,
                              void* d_out, int out_size) {
    (void)in_sizes; (void)n_in; (void)out_size;
    const float* x  = (const float*)d_in[0];
    const float* Wq = (const float*)d_in[1];
    const float* bq = (const float*)d_in[2];
    const float* Wk = (const float*)d_in[3];
    const float* bk = (const float*)d_in[4];
    const float* Wv = (const float*)d_in[5];
    const float* bv = (const float*)d_in[6];
    const float* Wo = (const float*)d_in[7];
    const float* bo = (const float*)d_in[8];
    float* out = (float*)d_out;

    float *q, *k, *v, *att, *wt;
    cudaGetSymbolAddress((void**)&q, g_q);
    cudaGetSymbolAddress((void**)&k, g_k);
    cudaGetSymbolAddress((void**)&v, g_v);
    cudaGetSymbolAddress((void**)&att, g_att);
    cudaGetSymbolAddress((void**)&wt, g_wt);
    float* wtq = wt;
    float* wtk = wt + (size_t)E * E;
    float* wtv = wt + 2 * (size_t)E * E;
    float* wto = wt + 3 * (size_t)E * E;

    cudaFuncSetAttribute(attn_kernel,
                         cudaFuncAttributeMaxDynamicSharedMemorySize, ATT_SMEM);

    dim3 tgrid(32, 32), tblk(32, 8);
    transpose1k<<<tgrid, tblk>>>(Wq, wtq);
    transpose1k<<<tgrid, tblk>>>(Wk, wtk);
    transpose1k<<<tgrid, tblk>>>(Wv, wtv);
    transpose1k<<<tgrid, tblk>>>(Wo, wto);

    dim3 ggrid(E / GN, MTOT / GM);   // (16, 32) = 512 CTAs
    gemm_tf32_kernel<<<ggrid, 256>>>(x, wtq, bq, q);
    gemm_tf32_kernel<<<ggrid, 256>>>(x, wtk, bk, k);
    gemm_tf32_kernel<<<ggrid, 256>>>(x, wtv, bv, v);

    dim3 agrid(SEQ / 128, H, BATCH);  // (16, 16, 2) = 512 CTAs
    attn_kernel<<<agrid, 256, ATT_SMEM>>>(q, k, v, att);

    gemm_tf32_kernel<<<ggrid, 256>>>(att, wto, bo, out);
}